// round 8
// baseline (speedup 1.0000x reference)
#include <cuda_runtime.h>

#define NN      262144          // 64^3
#define NNZ_TOT (7 * NN)
#define BS      128
#define CH      32              // batch chunk width
#define NCHUNK  (BS / CH)       // 4
#define RB      4096            // reduce-role blocks (64 n each)
#define PB      8192            // prep-role blocks (32 n each)

// Resident scratch: ypT + yhT = 64 MB, fits L2 with slack.
__device__ float  g_ypT[(size_t)NN * CH];   // y_pred chunk (N, 32)  32 MB
__device__ float  g_yhT[(size_t)NN * CH];   // Yhat  chunk (N, 32)  32 MB
__device__ double g_acc[5 * BS];            // s1..s5 per batch element

// ---- init: prep chunk 0 (transpose yp) + zero yhT + zero acc
// grid = PB, block = (32, 8)
__global__ void init_kernel(const float* __restrict__ yp) {
    __shared__ float tp[32][33];
    int n0 = blockIdx.x * 32;
    int tx = threadIdx.x, ty = threadIdx.y;
    int tid = ty * 32 + tx;
#pragma unroll
    for (int r = 0; r < 32; r += 8)
        tp[ty + r][tx] = __ldcs(yp + (size_t)(ty + r) * NN + n0 + tx);
    ((float4*)g_yhT)[(size_t)n0 * 8 + tid] = make_float4(0.f, 0.f, 0.f, 0.f);
    if (blockIdx.x == 0)
        for (int i = tid; i < 5 * BS; i += 256) g_acc[i] = 0.0;
    __syncthreads();
#pragma unroll
    for (int r = 0; r < 32; r += 8)
        g_ypT[(size_t)(n0 + ty + r) * 32 + tx] = tp[tx][ty + r];
}

// ---- per-chunk scatter: Yhat_c[:, r] += v * yp_c[:, c]   (L2-capped)
__global__ void scatter_chunk(const float* __restrict__ vals,
                              const int* __restrict__ rows,
                              const int* __restrict__ cols) {
    const float4* yp4 = (const float4*)g_ypT;
    float4*       yh4 = (float4*)g_yhT;
    int gid    = blockIdx.x * blockDim.x + threadIdx.x;
    int stride = gridDim.x * blockDim.x;
    int sub    = gid & 7;
    for (int q = gid >> 3; q < NNZ_TOT; q += (stride >> 3)) {
        int   r = __ldcs(rows + q);
        int   c = __ldcs(cols + q);
        float v = __ldcs(vals + q);
        float4 p = __ldg(&yp4[(size_t)c * 8 + sub]);
        atomicAdd(&yh4[(size_t)r * 8 + sub],
                  make_float4(v * p.x, v * p.y, v * p.z, v * p.w));
    }
}

// ---- fused: reduce-role (blocks < RB) for chunk b0, zeroing yhT as it
// reads; prep-role (blocks >= RB) transposes yp for chunk b0+CH.
// block = 256 threads.
__global__ void fused_rp(const float* __restrict__ yp,
                         const float* __restrict__ yt, int b0) {
    __shared__ float smT[64][33];      // also reused as prep tile (32x33 part)
    int tid  = threadIdx.x;

    if (blockIdx.x >= RB) {            // ---------------- prep role
        int pb = blockIdx.x - RB;
        int n0 = pb * 32;
        int tx = tid & 31, ty = tid >> 5;   // 32 x 8
        int b0p = b0 + CH;
#pragma unroll
        for (int r = 0; r < 32; r += 8)
            smT[ty + r][tx] = __ldcs(yp + (size_t)(b0p + ty + r) * NN + n0 + tx);
        __syncthreads();
#pragma unroll
        for (int r = 0; r < 32; r += 8)
            g_ypT[(size_t)(n0 + ty + r) * 32 + tx] = smT[tx][ty + r];
        return;
    }

    // ---------------- reduce role: 64 n rows per block
    __shared__ float smP[64][33];
    __shared__ float red[5][8][32];
    int lane = tid & 31;
    int w    = tid >> 5;

    // load yp & yt tiles (64 n x 32 b), transposed: j = batch, n local rows
    {
        int j  = tid >> 3;             // 0..31
        int c0 = tid & 7;
        const float4* ytr = (const float4*)(yt + (size_t)(b0 + j) * NN) + blockIdx.x * 16;
        const float4* ypr = (const float4*)(yp + (size_t)(b0 + j) * NN) + blockIdx.x * 16;
#pragma unroll
        for (int pass = 0; pass < 2; pass++) {
            int n4 = pass * 8 + c0;
            float4 v = __ldcs(&ytr[n4]);
            smT[n4 * 4 + 0][j] = v.x; smT[n4 * 4 + 1][j] = v.y;
            smT[n4 * 4 + 2][j] = v.z; smT[n4 * 4 + 3][j] = v.w;
            float4 u = __ldcs(&ypr[n4]);
            smP[n4 * 4 + 0][j] = u.x; smP[n4 * 4 + 1][j] = u.y;
            smP[n4 * 4 + 2][j] = u.z; smP[n4 * 4 + 3][j] = u.w;
        }
    }
    __syncthreads();

    float4* yh4 = (float4*)g_yhT;
    int j0   = (lane & 7) * 4;
    int nsub = lane >> 3;

    float a1[4] = {0, 0, 0, 0}, a2[4] = {0, 0, 0, 0}, a3[4] = {0, 0, 0, 0};
    float a4[4] = {0, 0, 0, 0}, a5[4] = {0, 0, 0, 0};

#pragma unroll
    for (int k2 = 0; k2 < 2; k2++) {
        int rg_l = w * 2 + k2;                        // 0..15 row-groups
        size_t f = ((size_t)blockIdx.x * 16 + rg_l) * 32 + lane;
        float4 h = yh4[f];
        yh4[f] = make_float4(0.f, 0.f, 0.f, 0.f);     // zero for next chunk
        int nl = rg_l * 4 + nsub;
        float t0 = smT[nl][j0 + 0], t1 = smT[nl][j0 + 1];
        float t2 = smT[nl][j0 + 2], t3 = smT[nl][j0 + 3];
        float p0 = smP[nl][j0 + 0], p1 = smP[nl][j0 + 1];
        float p2 = smP[nl][j0 + 2], p3 = smP[nl][j0 + 3];
        a1[0] += t0 * p0;  a1[1] += t1 * p1;  a1[2] += t2 * p2;  a1[3] += t3 * p3;
        a2[0] += p0 * h.x; a2[1] += p1 * h.y; a2[2] += p2 * h.z; a2[3] += p3 * h.w;
        a3[0] += t0 * t0;  a3[1] += t1 * t1;  a3[2] += t2 * t2;  a3[3] += t3 * t3;
        a4[0] += t0 * h.x; a4[1] += t1 * h.y; a4[2] += t2 * h.z; a4[3] += t3 * h.w;
        a5[0] += h.x * h.x; a5[1] += h.y * h.y; a5[2] += h.z * h.z; a5[3] += h.w * h.w;
    }

    // lanes {l, l+8, l+16, l+24} hold the same 4 batch columns
#pragma unroll
    for (int k = 0; k < 4; k++) {
#pragma unroll
        for (int d = 16; d >= 8; d >>= 1) {
            a1[k] += __shfl_down_sync(0xffffffffu, a1[k], d);
            a2[k] += __shfl_down_sync(0xffffffffu, a2[k], d);
            a3[k] += __shfl_down_sync(0xffffffffu, a3[k], d);
            a4[k] += __shfl_down_sync(0xffffffffu, a4[k], d);
            a5[k] += __shfl_down_sync(0xffffffffu, a5[k], d);
        }
    }

    if (lane < 8) {
#pragma unroll
        for (int k = 0; k < 4; k++) {
            red[0][w][lane * 4 + k] = a1[k];
            red[1][w][lane * 4 + k] = a2[k];
            red[2][w][lane * 4 + k] = a3[k];
            red[3][w][lane * 4 + k] = a4[k];
            red[4][w][lane * 4 + k] = a5[k];
        }
    }
    __syncthreads();

    if (tid < 160) {
        int acc = tid >> 5;
        int j   = tid & 31;
        float s = 0.f;
#pragma unroll
        for (int ww = 0; ww < 8; ww++) s += red[acc][ww][j];
        atomicAdd(&g_acc[acc * BS + b0 + j], (double)s);
    }
}

// ------------------------------------------------------------ final scalar
__global__ void final_kernel(float* out) {
    int b = threadIdx.x;            // 128 threads
    double s1 = g_acc[0 * BS + b];
    double s2 = g_acc[1 * BS + b];
    double s3 = g_acc[2 * BS + b];
    double s4 = g_acc[3 * BS + b];
    double s5 = g_acc[4 * BS + b];
    double c  = s1 / s2;
    double r  = s3 - 2.0 * c * s4 + c * c * s5;
    __shared__ double sh[128];
    sh[b] = r;
    __syncthreads();
    for (int s = 64; s > 0; s >>= 1) {
        if (b < s) sh[b] += sh[b + s];
        __syncthreads();
    }
    if (b == 0) out[0] = (float)(sh[0] / (double)BS);
}

extern "C" void kernel_launch(void* const* d_in, const int* in_sizes, int n_in,
                              void* d_out, int out_size) {
    const float* yp   = (const float*)d_in[0];
    const float* yt   = (const float*)d_in[1];
    const float* vals = (const float*)d_in[2];
    const int*   rows = (const int*)d_in[3];
    const int*   cols = (const int*)d_in[4];
    float*       out  = (float*)d_out;

    init_kernel<<<PB, dim3(32, 8)>>>(yp);
    for (int c = 0; c < NCHUNK; c++) {
        scatter_chunk<<<2368, 256>>>(vals, rows, cols);
        int grid = (c < NCHUNK - 1) ? (RB + PB) : RB;   // last chunk: no prep
        fused_rp<<<grid, 256>>>(yp, yt, c * CH);
    }
    final_kernel<<<1, BS>>>(out);
}

// round 9
// speedup vs baseline: 1.0999x; 1.0999x over previous
#include <cuda_runtime.h>

#define NN      262144          // 64^3
#define NNZ_TOT (7 * NN)
#define BS      128
#define CH      32              // batch chunk width
#define NCHUNK  (BS / CH)       // 4
#define SGRID   2368            // fused scatter+prep grid
#define NPREP   (SGRID / 8)     // 296 prep-role blocks
#define NTILES  (NN / 32)       // 8192 transpose tiles per chunk

// Double-buffered ypT (2x32 MB) + yhT (32 MB) = 96 MB resident.
__device__ float  g_ypT[2][(size_t)NN * CH];
__device__ float  g_yhT[(size_t)NN * CH];
__device__ double g_acc[5 * BS];

// ---- init: transpose chunk 0 into buf 0, zero yhT, zero acc
// grid = NTILES, block = (32, 8)
__global__ void init_kernel(const float* __restrict__ yp) {
    __shared__ float tp[32][33];
    int n0 = blockIdx.x * 32;
    int tx = threadIdx.x, ty = threadIdx.y;
    int tid = ty * 32 + tx;
#pragma unroll
    for (int r = 0; r < 32; r += 8)
        tp[ty + r][tx] = __ldcs(yp + (size_t)(ty + r) * NN + n0 + tx);
    ((float4*)g_yhT)[(size_t)n0 * 8 + tid] = make_float4(0.f, 0.f, 0.f, 0.f);
    if (blockIdx.x == 0)
        for (int i = tid; i < 5 * BS; i += 256) g_acc[i] = 0.0;
    __syncthreads();
#pragma unroll
    for (int r = 0; r < 32; r += 8)
        g_ypT[0][(size_t)(n0 + ty + r) * 32 + tx] = tp[tx][ty + r];
}

// ---- fused scatter(cur chunk) + prep(next chunk into other buffer).
// Every 8th block is prep-role (grid-stride over tiles); the rest scatter
// (grid-stride over nnz). Scatter keeps ypT[cur]/yhT hot in L2 while prep
// streams DRAM, so the two roles use disjoint bandwidth resources.
__global__ void scatter_prep(const float* __restrict__ vals,
                             const int* __restrict__ rows,
                             const int* __restrict__ cols,
                             const float* __restrict__ yp,
                             int cur, int b0next, int has_prep) {
    int tid = threadIdx.x;
    if (has_prep && (blockIdx.x & 7) == 7) {      // -------- prep role
        __shared__ float tp[32][33];
        float* dst = g_ypT[cur ^ 1];
        int pid = blockIdx.x >> 3;                // 0..NPREP-1
        int tx = tid & 31, ty = tid >> 5;         // 32 x 8
        for (int t = pid; t < NTILES; t += NPREP) {
            int n0 = t * 32;
#pragma unroll
            for (int r = 0; r < 32; r += 8)
                tp[ty + r][tx] = __ldcs(yp + (size_t)(b0next + ty + r) * NN + n0 + tx);
            __syncthreads();
#pragma unroll
            for (int r = 0; r < 32; r += 8)
                dst[(size_t)(n0 + ty + r) * 32 + tx] = tp[tx][ty + r];
            __syncthreads();
        }
        return;
    }
    // ---------------- scatter role
    const float4* yp4 = (const float4*)g_ypT[cur];
    float4*       yh4 = (float4*)g_yhT;
    int nsb  = has_prep ? (SGRID - NPREP) : SGRID;        // scatter blocks
    int sid  = has_prep ? (blockIdx.x - (blockIdx.x >> 3)) : blockIdx.x;
    int gid    = sid * 256 + tid;
    int stride = nsb * 256;
    int sub    = gid & 7;
    for (int q = gid >> 3; q < NNZ_TOT; q += (stride >> 3)) {
        int   r = __ldcs(rows + q);
        int   c = __ldcs(cols + q);
        float v = __ldcs(vals + q);
        float4 p = __ldg(&yp4[(size_t)c * 8 + sub]);
        atomicAdd(&yh4[(size_t)r * 8 + sub],
                  make_float4(v * p.x, v * p.y, v * p.z, v * p.w));
    }
}

// ---- per-chunk reduce: s1..s5; ypT[cur]/yhT float4 from L2; y_true
// streamed through conflict-free smem transpose tile. Zeros yhT for the
// next chunk's scatter. grid = NN/128, block = 256.
__global__ void __launch_bounds__(256, 6)
reduce_chunk(const float* __restrict__ yt, int b0, int cur) {
    __shared__ float smT[128][33];
    __shared__ float red[5][8][32];
    int tid  = threadIdx.x;            // 256 = 8 warps
    int lane = tid & 31;
    int w    = tid >> 5;

    // Load yt tile (128 n x 32 b), transposed into smem.
    {
        int j  = tid >> 3;
        int c0 = tid & 7;
        const float4* ytr = (const float4*)(yt + (size_t)(b0 + j) * NN) + blockIdx.x * 32;
#pragma unroll
        for (int pass = 0; pass < 4; pass++) {
            int n4 = pass * 8 + c0;
            float4 v = __ldcs(&ytr[n4]);
            smT[n4 * 4 + 0][j] = v.x;
            smT[n4 * 4 + 1][j] = v.y;
            smT[n4 * 4 + 2][j] = v.z;
            smT[n4 * 4 + 3][j] = v.w;
        }
    }
    __syncthreads();

    const float4* yp4 = (const float4*)g_ypT[cur];
    float4*       yh4 = (float4*)g_yhT;

    int j0   = (lane & 7) * 4;
    int nsub = lane >> 3;

    float a1[4] = {0, 0, 0, 0}, a2[4] = {0, 0, 0, 0}, a3[4] = {0, 0, 0, 0};
    float a4[4] = {0, 0, 0, 0}, a5[4] = {0, 0, 0, 0};

#pragma unroll
    for (int k2 = 0; k2 < 4; k2++) {
        int rg_l = w * 4 + k2;                       // local row-group 0..31
        size_t f = ((size_t)blockIdx.x * 32 + rg_l) * 32 + lane;
        float4 p = __ldg(&yp4[f]);
        float4 h = yh4[f];
        yh4[f] = make_float4(0.f, 0.f, 0.f, 0.f);    // zero for next scatter
        int nl = rg_l * 4 + nsub;
        float t0 = smT[nl][j0 + 0];
        float t1 = smT[nl][j0 + 1];
        float t2 = smT[nl][j0 + 2];
        float t3 = smT[nl][j0 + 3];
        a1[0] += t0 * p.x; a1[1] += t1 * p.y; a1[2] += t2 * p.z; a1[3] += t3 * p.w;
        a2[0] += p.x * h.x; a2[1] += p.y * h.y; a2[2] += p.z * h.z; a2[3] += p.w * h.w;
        a3[0] += t0 * t0;  a3[1] += t1 * t1;  a3[2] += t2 * t2;  a3[3] += t3 * t3;
        a4[0] += t0 * h.x; a4[1] += t1 * h.y; a4[2] += t2 * h.z; a4[3] += t3 * h.w;
        a5[0] += h.x * h.x; a5[1] += h.y * h.y; a5[2] += h.z * h.z; a5[3] += h.w * h.w;
    }

    // lanes {l, l+8, l+16, l+24} hold the same 4 batch columns
#pragma unroll
    for (int k = 0; k < 4; k++) {
#pragma unroll
        for (int d = 16; d >= 8; d >>= 1) {
            a1[k] += __shfl_down_sync(0xffffffffu, a1[k], d);
            a2[k] += __shfl_down_sync(0xffffffffu, a2[k], d);
            a3[k] += __shfl_down_sync(0xffffffffu, a3[k], d);
            a4[k] += __shfl_down_sync(0xffffffffu, a4[k], d);
            a5[k] += __shfl_down_sync(0xffffffffu, a5[k], d);
        }
    }

    if (lane < 8) {
#pragma unroll
        for (int k = 0; k < 4; k++) {
            red[0][w][lane * 4 + k] = a1[k];
            red[1][w][lane * 4 + k] = a2[k];
            red[2][w][lane * 4 + k] = a3[k];
            red[3][w][lane * 4 + k] = a4[k];
            red[4][w][lane * 4 + k] = a5[k];
        }
    }
    __syncthreads();

    if (tid < 160) {
        int acc = tid >> 5;
        int j   = tid & 31;
        float s = 0.f;
#pragma unroll
        for (int ww = 0; ww < 8; ww++) s += red[acc][ww][j];
        atomicAdd(&g_acc[acc * BS + b0 + j], (double)s);
    }
}

// ------------------------------------------------------------ final scalar
__global__ void final_kernel(float* out) {
    int b = threadIdx.x;            // 128 threads
    double s1 = g_acc[0 * BS + b];
    double s2 = g_acc[1 * BS + b];
    double s3 = g_acc[2 * BS + b];
    double s4 = g_acc[3 * BS + b];
    double s5 = g_acc[4 * BS + b];
    double c  = s1 / s2;
    double r  = s3 - 2.0 * c * s4 + c * c * s5;
    __shared__ double sh[128];
    sh[b] = r;
    __syncthreads();
    for (int s = 64; s > 0; s >>= 1) {
        if (b < s) sh[b] += sh[b + s];
        __syncthreads();
    }
    if (b == 0) out[0] = (float)(sh[0] / (double)BS);
}

extern "C" void kernel_launch(void* const* d_in, const int* in_sizes, int n_in,
                              void* d_out, int out_size) {
    const float* yp   = (const float*)d_in[0];
    const float* yt   = (const float*)d_in[1];
    const float* vals = (const float*)d_in[2];
    const int*   rows = (const int*)d_in[3];
    const int*   cols = (const int*)d_in[4];
    float*       out  = (float*)d_out;

    init_kernel<<<NTILES, dim3(32, 8)>>>(yp);
    for (int c = 0; c < NCHUNK; c++) {
        int cur = c & 1;
        scatter_prep<<<SGRID, 256>>>(vals, rows, cols, yp,
                                     cur, (c + 1) * CH, c < NCHUNK - 1);
        reduce_chunk<<<NN / 128, 256>>>(yt, c * CH, cur);
    }
    final_kernel<<<1, BS>>>(out);
}

// round 10
// speedup vs baseline: 1.1435x; 1.0397x over previous
#include <cuda_runtime.h>

#define NN      262144          // 64^3
#define NNZ_TOT (7 * NN)
#define BS      128
#define CH      32              // batch chunk width
#define NCHUNK  (BS / CH)       // 4

// Resident scratch: ypT + yhT = 64 MB, fits L2 with slack.
__device__ float  g_ypT[(size_t)NN * CH];   // y_pred chunk (N, 32)  32 MB
__device__ float  g_yhT[(size_t)NN * CH];   // Yhat  chunk (N, 32)  32 MB
__device__ double g_acc[5 * BS];            // s1..s5 per batch element

// ---- init (chunk 0): transpose yp, zero yhT, zero acc
// grid = NN/32, block = (32, 8)
__global__ void init_kernel(const float* __restrict__ yp) {
    __shared__ float tp[32][33];
    int n0 = blockIdx.x * 32;
    int tx = threadIdx.x, ty = threadIdx.y;
    int tid = ty * 32 + tx;
#pragma unroll
    for (int r = 0; r < 32; r += 8)
        tp[ty + r][tx] = __ldcs(yp + (size_t)(ty + r) * NN + n0 + tx);
    ((float4*)g_yhT)[(size_t)n0 * 8 + tid] = make_float4(0.f, 0.f, 0.f, 0.f);
    if (blockIdx.x == 0)
        for (int i = tid; i < 5 * BS; i += 256) g_acc[i] = 0.0;
    __syncthreads();
#pragma unroll
    for (int r = 0; r < 32; r += 8)
        g_ypT[(size_t)(n0 + ty + r) * 32 + tx] = tp[tx][ty + r];
}

// ---- prep (chunks 1..3): transpose yp only; yhT was zeroed by reduce.
__global__ void prep_chunk(const float* __restrict__ yp, int b0) {
    __shared__ float tp[32][33];
    int n0 = blockIdx.x * 32;
    int tx = threadIdx.x, ty = threadIdx.y;
#pragma unroll
    for (int r = 0; r < 32; r += 8)
        tp[ty + r][tx] = __ldcs(yp + (size_t)(b0 + ty + r) * NN + n0 + tx);
    __syncthreads();
#pragma unroll
    for (int r = 0; r < 32; r += 8)
        g_ypT[(size_t)(n0 + ty + r) * 32 + tx] = tp[tx][ty + r];
}

// ---- per-chunk scatter: Yhat_c[:, r] += v * yp_c[:, c]   (L2-capped, R7)
__global__ void scatter_chunk(const float* __restrict__ vals,
                              const int* __restrict__ rows,
                              const int* __restrict__ cols) {
    const float4* yp4 = (const float4*)g_ypT;
    float4*       yh4 = (float4*)g_yhT;
    int gid    = blockIdx.x * blockDim.x + threadIdx.x;
    int stride = gridDim.x * blockDim.x;
    int sub    = gid & 7;
    for (int q = gid >> 3; q < NNZ_TOT; q += (stride >> 3)) {
        int   r = __ldcs(rows + q);
        int   c = __ldcs(cols + q);
        float v = __ldcs(vals + q);
        float4 p = __ldg(&yp4[(size_t)c * 8 + sub]);
        atomicAdd(&yh4[(size_t)r * 8 + sub],
                  make_float4(v * p.x, v * p.y, v * p.z, v * p.w));
    }
}

// ---- per-chunk reduce: s1..s5; ypT/yhT float4 from L2-resident layout;
// y_true streamed through conflict-free smem transpose tile. Zeros yhT
// for the next chunk's scatter. grid = NN/128, block = 256.
__global__ void __launch_bounds__(256, 6)
reduce_chunk(const float* __restrict__ yt, int b0) {
    __shared__ float smT[128][33];
    __shared__ float red[5][8][32];
    int tid  = threadIdx.x;            // 256 = 8 warps
    int lane = tid & 31;
    int w    = tid >> 5;

    // Load yt tile (128 n x 32 b), transposed into smem.
    {
        int j  = tid >> 3;
        int c0 = tid & 7;
        const float4* ytr = (const float4*)(yt + (size_t)(b0 + j) * NN) + blockIdx.x * 32;
#pragma unroll
        for (int pass = 0; pass < 4; pass++) {
            int n4 = pass * 8 + c0;
            float4 v = __ldcs(&ytr[n4]);
            smT[n4 * 4 + 0][j] = v.x;
            smT[n4 * 4 + 1][j] = v.y;
            smT[n4 * 4 + 2][j] = v.z;
            smT[n4 * 4 + 3][j] = v.w;
        }
    }
    __syncthreads();

    const float4* yp4 = (const float4*)g_ypT;
    float4*       yh4 = (float4*)g_yhT;

    int j0   = (lane & 7) * 4;
    int nsub = lane >> 3;

    float a1[4] = {0, 0, 0, 0}, a2[4] = {0, 0, 0, 0}, a3[4] = {0, 0, 0, 0};
    float a4[4] = {0, 0, 0, 0}, a5[4] = {0, 0, 0, 0};

#pragma unroll
    for (int k2 = 0; k2 < 4; k2++) {
        int rg_l = w * 4 + k2;                       // local row-group 0..31
        size_t f = ((size_t)blockIdx.x * 32 + rg_l) * 32 + lane;
        float4 p = __ldg(&yp4[f]);
        float4 h = yh4[f];
        yh4[f] = make_float4(0.f, 0.f, 0.f, 0.f);    // zero for next scatter
        int nl = rg_l * 4 + nsub;
        float t0 = smT[nl][j0 + 0];
        float t1 = smT[nl][j0 + 1];
        float t2 = smT[nl][j0 + 2];
        float t3 = smT[nl][j0 + 3];
        a1[0] += t0 * p.x; a1[1] += t1 * p.y; a1[2] += t2 * p.z; a1[3] += t3 * p.w;
        a2[0] += p.x * h.x; a2[1] += p.y * h.y; a2[2] += p.z * h.z; a2[3] += p.w * h.w;
        a3[0] += t0 * t0;  a3[1] += t1 * t1;  a3[2] += t2 * t2;  a3[3] += t3 * t3;
        a4[0] += t0 * h.x; a4[1] += t1 * h.y; a4[2] += t2 * h.z; a4[3] += t3 * h.w;
        a5[0] += h.x * h.x; a5[1] += h.y * h.y; a5[2] += h.z * h.z; a5[3] += h.w * h.w;
    }

    // lanes {l, l+8, l+16, l+24} hold the same 4 batch columns
#pragma unroll
    for (int k = 0; k < 4; k++) {
#pragma unroll
        for (int d = 16; d >= 8; d >>= 1) {
            a1[k] += __shfl_down_sync(0xffffffffu, a1[k], d);
            a2[k] += __shfl_down_sync(0xffffffffu, a2[k], d);
            a3[k] += __shfl_down_sync(0xffffffffu, a3[k], d);
            a4[k] += __shfl_down_sync(0xffffffffu, a4[k], d);
            a5[k] += __shfl_down_sync(0xffffffffu, a5[k], d);
        }
    }

    if (lane < 8) {
#pragma unroll
        for (int k = 0; k < 4; k++) {
            red[0][w][lane * 4 + k] = a1[k];
            red[1][w][lane * 4 + k] = a2[k];
            red[2][w][lane * 4 + k] = a3[k];
            red[3][w][lane * 4 + k] = a4[k];
            red[4][w][lane * 4 + k] = a5[k];
        }
    }
    __syncthreads();

    if (tid < 160) {
        int acc = tid >> 5;
        int j   = tid & 31;
        float s = 0.f;
#pragma unroll
        for (int ww = 0; ww < 8; ww++) s += red[acc][ww][j];
        atomicAdd(&g_acc[acc * BS + b0 + j], (double)s);
    }
}

// ------------------------------------------------------------ final scalar
__global__ void final_kernel(float* out) {
    int b = threadIdx.x;            // 128 threads
    double s1 = g_acc[0 * BS + b];
    double s2 = g_acc[1 * BS + b];
    double s3 = g_acc[2 * BS + b];
    double s4 = g_acc[3 * BS + b];
    double s5 = g_acc[4 * BS + b];
    double c  = s1 / s2;
    double r  = s3 - 2.0 * c * s4 + c * c * s5;
    __shared__ double sh[128];
    sh[b] = r;
    __syncthreads();
    for (int s = 64; s > 0; s >>= 1) {
        if (b < s) sh[b] += sh[b + s];
        __syncthreads();
    }
    if (b == 0) out[0] = (float)(sh[0] / (double)BS);
}

extern "C" void kernel_launch(void* const* d_in, const int* in_sizes, int n_in,
                              void* d_out, int out_size) {
    const float* yp   = (const float*)d_in[0];
    const float* yt   = (const float*)d_in[1];
    const float* vals = (const float*)d_in[2];
    const int*   rows = (const int*)d_in[3];
    const int*   cols = (const int*)d_in[4];
    float*       out  = (float*)d_out;

    init_kernel<<<NN / 32, dim3(32, 8)>>>(yp);
    for (int c = 0; c < NCHUNK; c++) {
        if (c > 0)
            prep_chunk<<<NN / 32, dim3(32, 8)>>>(yp, c * CH);
        scatter_chunk<<<2368, 256>>>(vals, rows, cols);
        reduce_chunk<<<NN / 128, 256>>>(yt, c * CH);
    }
    final_kernel<<<1, BS>>>(out);
}